// round 6
// baseline (speedup 1.0000x reference)
#include <cuda_runtime.h>
#include <math.h>

#define GDIM 128
#define G3 (GDIM*GDIM*GDIM)
#define NPART 4096
#define NKEY 512           // 64 c0-bins (width 2) x 8 c1-subbins (width 16)
#define NBLK 32            // sort blocks (128 particles each)

// Scratch (__device__ globals, no allocation)
__device__ float4 g_ps[NPART * 2];      // [2p]=(gp0,gp1,gp2,omega) [2p+1]=(em0..3)
__device__ int    g_pcs[NPART + 32];    // packed floor cell
__device__ int    g_bs2[NKEY + 1];      // key -> global start offset
__device__ int    g_hist[NBLK * NKEY];  // per-block key histograms
__device__ int    g_boff[NBLK * NKEY];  // per-block per-key exclusive offsets

__device__ __forceinline__ int particle_key(const float* pos, int i,
                                            int& pc, float& gp0, float& gp1, float& gp2) {
    gp0 = (pos[3*i+0] + 1.0f) * 63.5f;
    gp1 = (pos[3*i+1] + 1.0f) * 63.5f;
    gp2 = (pos[3*i+2] + 1.0f) * 63.5f;
    const int c0 = min(max((int)floorf(gp0), 0), GDIM-1);
    const int c1 = min(max((int)floorf(gp1), 0), GDIM-1);
    const int c2 = min(max((int)floorf(gp2), 0), GDIM-1);
    pc = c0 | (c1 << 8) | (c2 << 16);
    return ((c0 >> 1) << 3) | (c1 >> 4);
}

// ---------------------------------------------------------------------------
// Sort stage 1: per-block key histograms (32 blocks x 128 particles).
// ---------------------------------------------------------------------------
__global__ void __launch_bounds__(128)
hist_kernel(const float* __restrict__ pos) {
    __shared__ int h[NKEY];
    const int tid = threadIdx.x;
#pragma unroll
    for (int k = 0; k < NKEY / 128; k++) h[tid + k * 128] = 0;
    __syncthreads();
    int pc; float a, b, c;
    const int key = particle_key(pos, blockIdx.x * 128 + tid, pc, a, b, c);
    atomicAdd(&h[key], 1);
    __syncthreads();
#pragma unroll
    for (int k = 0; k < NKEY / 128; k++) {
        const int t = tid + k * 128;
        g_hist[blockIdx.x * NKEY + t] = h[t];
    }
}

// ---------------------------------------------------------------------------
// Sort stage 2: per-key prefix across blocks + global 512-key exclusive scan.
// ---------------------------------------------------------------------------
__global__ void __launch_bounds__(512)
offsets_kernel() {
    __shared__ int tot[NKEY];
    __shared__ int wtot[16];
    const int t    = threadIdx.x;
    const int w    = t >> 5;
    const int lane = t & 31;
    const unsigned FULL = 0xffffffffu;

    int s = 0;
#pragma unroll
    for (int b = 0; b < NBLK; b++) {
        const int v = g_hist[b * NKEY + t];
        g_boff[b * NKEY + t] = s;
        s += v;
    }
    tot[t] = s;
    __syncthreads();

    int vin = tot[t];
    const int v0 = vin;
#pragma unroll
    for (int d = 1; d < 32; d <<= 1) {
        const int u = __shfl_up_sync(FULL, vin, d);
        if (lane >= d) vin += u;
    }
    if (lane == 31) wtot[w] = vin;
    __syncthreads();
    if (t == 0) {
        int c = 0;
#pragma unroll
        for (int i = 0; i < 16; i++) { const int x = wtot[i]; wtot[i] = c; c += x; }
    }
    __syncthreads();
    g_bs2[t] = wtot[w] + vin - v0;   // global exclusive prefix
    if (t == 0) g_bs2[NKEY] = NPART;
}

// ---------------------------------------------------------------------------
// Sort stage 3: stable scatter (32 blocks x 128 threads = 4 warps).
// ---------------------------------------------------------------------------
__global__ void __launch_bounds__(128)
scatter_kernel(const float* __restrict__ pos,
               const float* __restrict__ inten,
               const float* __restrict__ emo) {
    __shared__ int wcnt[4][NKEY];
    const int tid  = threadIdx.x;
    const int w    = tid >> 5;
    const int lane = tid & 31;
    const unsigned FULL = 0xffffffffu;

#pragma unroll
    for (int k = 0; k < 4 * NKEY / 128; k++) ((int*)wcnt)[tid + k * 128] = 0;
    __syncthreads();

    const int i = blockIdx.x * 128 + tid;
    int pc; float gp0, gp1, gp2;
    const int key = particle_key(pos, i, pc, gp0, gp1, gp2);
    const unsigned m = __match_any_sync(FULL, key);
    const int r = __popc(m & ((1u << lane) - 1u));
    if (r == 0) wcnt[w][key] = __popc(m);
    __syncthreads();

#pragma unroll
    for (int k = 0; k < NKEY / 128; k++) {
        const int t = tid + k * 128;
        int s = 0;
#pragma unroll
        for (int wi = 0; wi < 4; wi++) { const int v = wcnt[wi][t]; wcnt[wi][t] = s; s += v; }
    }
    __syncthreads();

    const int p = g_bs2[key] + g_boff[blockIdx.x * NKEY + key] + wcnt[w][key] + r;
    g_pcs[p]      = pc;
    g_ps[2*p + 0] = make_float4(gp0, gp1, gp2, inten[i] * 0.01f);
    g_ps[2*p + 1] = make_float4(emo[4*i+0], emo[4*i+1], emo[4*i+2], emo[4*i+3]);
}

// ---------------------------------------------------------------------------
// TWO warps per sample (one block of 64 threads = 1 sample). Each lane owns
// one of the 32 needed cells (8 trilinear corners + 24 face neighbors).
// Warp w scans row segments r0+w, r0+w+2, ... ; partials combined in smem.
// Hit extraction is unrolled x2 with shfl-free bodies (broadcast LDG of the
// packed cell instead of a serial SHFL).
// ---------------------------------------------------------------------------
__global__ void __launch_bounds__(64)
main_kernel(const float* __restrict__ spos,
            const float* __restrict__ H0,
            const float* __restrict__ E0,
            float* __restrict__ out) {
    __shared__ float sv[2][5][64];
    const unsigned FULL = 0xffffffffu;
    const int wib  = threadIdx.x >> 5;
    const int lane = threadIdx.x & 31;
    const int s    = blockIdx.x;

    const float px = spos[3*s+0];
    const float py = spos[3*s+1];
    const float pz = spos[3*s+2];
    // grid axis0 <- comp2, axis1 <- comp1, axis2 <- comp0 (reference transpose)
    const float t0 = fminf(fmaxf((pz + 1.0f) * 63.5f, 0.0f), 127.0f);
    const float t1 = fminf(fmaxf((py + 1.0f) * 63.5f, 0.0f), 127.0f);
    const float t2 = fminf(fmaxf((px + 1.0f) * 63.5f, 0.0f), 127.0f);
    const int i0 = (int)floorf(t0); const float f0 = t0 - (float)i0;
    const int i1 = (int)floorf(t1); const float f1 = t1 - (float)i1;
    const int i2 = (int)floorf(t2); const float f2 = t2 - (float)i2;

    // lane -> block coords (b0,b1,b2), covering the 32 needed cells
    int b0, b1, b2;
    if (lane < 8) {
        b0 = 1 + ((lane >> 2) & 1); b1 = 1 + ((lane >> 1) & 1); b2 = 1 + (lane & 1);
    } else {
        const int idx = lane - 8, axis = idx >> 3, rest = idx & 7;
        const int s3 = ((rest >> 2) & 1) * 3;
        const int u = 1 + ((rest >> 1) & 1), v = 1 + (rest & 1);
        b0 = (axis == 0) ? s3 : u;
        b1 = (axis == 1) ? s3 : ((axis == 0) ? u : v);
        b2 = (axis == 2) ? s3 : v;
    }
    const int gc0 = min(max(i0 - 1 + b0, 0), 127);
    const int gc1 = min(max(i1 - 1 + b1, 0), 127);
    const int gc2 = min(max(i2 - 1 + b2, 0), 127);
    const float gcf0 = (float)gc0, gcf1 = (float)gc1, gcf2 = (float)gc2;
    const unsigned gcpack = (unsigned)(gc0 | (gc1 << 8) | (gc2 << 16));

    // particle-window (covers all 32 cells)
    const int lo0 = min(max(i0 - 1, 0), 127) - 9, hi0 = min(max(i0 + 2, 0), 127) + 9;
    const int lo1 = min(max(i1 - 1, 0), 127) - 9, hi1 = min(max(i1 + 2, 0), 127) + 9;
    const int lo2 = min(max(i2 - 1, 0), 127) - 9, hi2 = min(max(i2 + 2, 0), 127) + 9;
    const unsigned sp0 = (unsigned)(hi0 - lo0);
    const unsigned sp1 = (unsigned)(hi1 - lo1);
    const unsigned sp2 = (unsigned)(hi2 - lo2);

    const int r0  = max(lo0, 0) >> 1;
    const int r1  = min(hi0, 127) >> 1;
    const int slo = max(lo1, 0) >> 4;
    const int shi = min(hi1, 127) >> 4;

    float aH = 0.f, aE0 = 0.f, aE1 = 0.f, aE2 = 0.f, aE3 = 0.f;

    // shfl-free per-hit body (window check via broadcast reload of g_pcs)
    auto body = [&](int idx, bool valid) {
        const float4 A  = __ldg(&g_ps[2*idx + 0]);
        const float4 Em = __ldg(&g_ps[2*idx + 1]);
        const unsigned pcj = (unsigned)__ldg(&g_pcs[idx]);
        const unsigned diff = __vabsdiffu4(pcj, gcpack);
        const bool in = valid & (__vcmpleu4(diff, 0x09090909u) == 0xFFFFFFFFu);
        const float d0 = gcf0 - A.x;
        const float d1 = gcf1 - A.y;
        const float d2 = gcf2 - A.z;
        const float ssum = fmaf(d0, d0, fmaf(d1, d1, d2 * d2));
        const float e = __expf(ssum * -0.048828125f);
        float wv = in ? A.w : 0.0f;
        wv *= e;
        aH  += wv;
        aE0 += wv * Em.x;  aE1 += wv * Em.y;
        aE2 += wv * Em.z;  aE3 += wv * Em.w;
    };

    for (int r = r0 + wib; r <= r1; r += 2) {
        const int rb = r << 3;
        const int j0 = g_bs2[rb + slo];
        const int j1 = g_bs2[rb + shi + 1];
        for (int base = j0 & ~31; base < j1; base += 32) {
            const int idx = base + lane;
            const int pcv = g_pcs[idx];
            const int c0 = pcv & 255, c1 = (pcv >> 8) & 255, c2 = (pcv >> 16) & 255;
            const bool hit = ((unsigned)(c0 - lo0) <= sp0) &
                             ((unsigned)(c1 - lo1) <= sp1) &
                             ((unsigned)(c2 - lo2) <= sp2) &
                             (idx >= j0) & (idx < j1);
            unsigned msk = __ballot_sync(FULL, hit);
            while (msk) {
                const int jA = __ffs(msk) - 1;
                msk &= msk - 1;
                const bool hasB = (msk != 0);
                const int jB = hasB ? (__ffs(msk) - 1) : jA;
                msk &= msk - 1;
                body(base + jA, true);
                body(base + jB, hasB);
            }
        }
    }

    // stash partials (warp 0 also adds base grid values)
    const int ci   = b0 * 16 + b1 * 4 + b2;
    const int flat = (gc0 * GDIM + gc1) * GDIM + gc2;
    if (wib == 0) {
        sv[0][0][ci] = aH  + __ldg(&H0[flat]);
        sv[0][1][ci] = aE0 + __ldg(&E0[0*G3 + flat]);
        sv[0][2][ci] = aE1 + __ldg(&E0[1*G3 + flat]);
        sv[0][3][ci] = aE2 + __ldg(&E0[2*G3 + flat]);
        sv[0][4][ci] = aE3 + __ldg(&E0[3*G3 + flat]);
    } else {
        sv[1][0][ci] = aH;
        sv[1][1][ci] = aE0;
        sv[1][2][ci] = aE1;
        sv[1][3][ci] = aE2;
        sv[1][4][ci] = aE3;
    }
    __syncthreads();
    if (wib == 0) {
#pragma unroll
        for (int ch = 0; ch < 5; ch++) sv[0][ch][ci] += sv[1][ch][ci];
    }
    __syncthreads();
    if (wib != 0) return;

    // diffusion step + ReLU + trilinear reduce (8 corner lanes of warp 0)
#pragma unroll
    for (int ch = 0; ch < 5; ch++) {
        float part = 0.0f;
        if (lane < 8) {
            const int d0 = (lane >> 2) & 1, d1c = (lane >> 1) & 1, d2c = lane & 1;
            const int cc = (1 + d0) * 16 + (1 + d1c) * 4 + (1 + d2c);
            const float* v = sv[0][ch];
            const float c = v[cc];
            const float lap = v[cc-16] + v[cc+16] + v[cc-4] + v[cc+4]
                            + v[cc-1]  + v[cc+1]  - 6.0f * c;
            float val;
            if (ch == 0) val = c * (1.0f - 5e-5f) + 0.002f * lap;
            else         val = c * (1.0f - 5e-5f) + 5e-5f + 0.001f * lap;
            val = fmaxf(val, 0.0f);
            const float wq = (d0  ? f0 : 1.0f - f0)
                           * (d1c ? f1 : 1.0f - f1)
                           * (d2c ? f2 : 1.0f - f2);
            part = val * wq;
        }
        part += __shfl_down_sync(FULL, part, 4);
        part += __shfl_down_sync(FULL, part, 2);
        part += __shfl_down_sync(FULL, part, 1);
        if (lane == 0) out[s * 5 + ch] = part;
    }
}

extern "C" void kernel_launch(void* const* d_in, const int* in_sizes, int n_in,
                              void* d_out, int out_size) {
    const float* positions   = (const float*)d_in[0];  // (4096,3)
    const float* intensities = (const float*)d_in[1];  // (4096,)
    const float* emotions    = (const float*)d_in[2];  // (4096,4)
    const float* sample_pos  = (const float*)d_in[3];  // (8,1024,3)
    const float* H0          = (const float*)d_in[4];  // (128,128,128)
    const float* E0          = (const float*)d_in[5];  // (4,128,128,128)
    float* out = (float*)d_out;                        // (8,1024,5)

    hist_kernel<<<NBLK, 128>>>(positions);
    offsets_kernel<<<1, 512>>>();
    scatter_kernel<<<NBLK, 128>>>(positions, intensities, emotions);
    main_kernel<<<8192, 64>>>(sample_pos, H0, E0, out);
    (void)in_sizes; (void)n_in; (void)out_size;
}

// round 7
// speedup vs baseline: 1.1695x; 1.1695x over previous
#include <cuda_runtime.h>
#include <math.h>

#define GDIM 128
#define G3 (GDIM*GDIM*GDIM)
#define NPART 4096
#define NKEY 512           // 64 c0-bins (width 2) x 8 c1-subbins (width 16)
#define NBLK 32            // sort blocks (128 particles each)

// Scratch (__device__ globals, no allocation)
__device__ float4 g_ps[NPART * 2];      // [2p]=(gp0,gp1,gp2,omega) [2p+1]=(em0..3)
__device__ int    g_pcs[NPART + 32];    // packed floor cell
__device__ int    g_bs2[NKEY + 1];      // key -> global start offset
__device__ int    g_hist[NBLK * NKEY];  // per-block key histograms
__device__ int    g_bar1;               // spin barrier (self-resetting)
__device__ int    g_bar2;

// ---------------------------------------------------------------------------
// Fused sort: hist + cross-block offsets + stable scatter in ONE kernel.
// 32 blocks x 128 threads; blocks rendezvous at a device spin barrier
// (32 blocks << 148 SMs, always co-resident). Counters are reset by the
// last-arriving block so every replay starts from the same state.
// ---------------------------------------------------------------------------
__global__ void __launch_bounds__(128)
fsort_kernel(const float* __restrict__ pos,
             const float* __restrict__ inten,
             const float* __restrict__ emo) {
    __shared__ int h[NKEY];
    __shared__ int bs2s[NKEY];
    __shared__ int boffm[NKEY];
    __shared__ int wcnt[4][NKEY];
    __shared__ int wsum[4];
    const int tid  = threadIdx.x;
    const int w    = tid >> 5;
    const int lane = tid & 31;
    const int myb  = blockIdx.x;
    const unsigned FULL = 0xffffffffu;

#pragma unroll
    for (int k = 0; k < NKEY / 128; k++) h[tid + k * 128] = 0;
    __syncthreads();

    // ---- phase A: key + payload + block histogram ----
    const int i = myb * 128 + tid;
    const float gp0 = (pos[3*i+0] + 1.0f) * 63.5f;
    const float gp1 = (pos[3*i+1] + 1.0f) * 63.5f;
    const float gp2 = (pos[3*i+2] + 1.0f) * 63.5f;
    const int c0 = min(max((int)floorf(gp0), 0), GDIM-1);
    const int c1 = min(max((int)floorf(gp1), 0), GDIM-1);
    const int c2 = min(max((int)floorf(gp2), 0), GDIM-1);
    const int pc  = c0 | (c1 << 8) | (c2 << 16);
    const int key = ((c0 >> 1) << 3) | (c1 >> 4);
    atomicAdd(&h[key], 1);
    const float4 pA = make_float4(gp0, gp1, gp2, inten[i] * 0.01f);
    const float4 pE = make_float4(emo[4*i+0], emo[4*i+1], emo[4*i+2], emo[4*i+3]);
    __syncthreads();
#pragma unroll
    for (int k = 0; k < NKEY / 128; k++) {
        const int t = tid + k * 128;
        g_hist[myb * NKEY + t] = h[t];
    }
    __threadfence();

    // ---- barrier: all block histograms visible ----
    if (tid == 0) {
        atomicAdd(&g_bar1, 1);
        while (*(volatile int*)&g_bar1 < NBLK) { }
    }
    __syncthreads();
    __threadfence();

    // ---- phase B: per-key cross-block sums; thread t owns keys 4t..4t+3 ----
    int totk[4], bok[4];
#pragma unroll
    for (int k = 0; k < 4; k++) {
        const int kk = tid * 4 + k;
        int s = 0, mine = 0;
#pragma unroll
        for (int b = 0; b < NBLK; b++) {
            if (b == myb) mine = s;
            s += g_hist[b * NKEY + kk];
        }
        totk[k] = s; bok[k] = mine;
    }
    const int tsum = totk[0] + totk[1] + totk[2] + totk[3];
    int inc = tsum;
#pragma unroll
    for (int d = 1; d < 32; d <<= 1) {
        const int u = __shfl_up_sync(FULL, inc, d);
        if (lane >= d) inc += u;
    }
    if (lane == 31) wsum[w] = inc;
    __syncthreads();
    if (tid == 0) {
        int s = 0;
#pragma unroll
        for (int q = 0; q < 4; q++) { const int x = wsum[q]; wsum[q] = s; s += x; }
    }
    __syncthreads();
    int run = wsum[w] + inc - tsum;        // exclusive prefix for key 4*tid
#pragma unroll
    for (int k = 0; k < 4; k++) {
        const int kk = tid * 4 + k;
        bs2s[kk]  = run;
        boffm[kk] = bok[k];
        run += totk[k];
    }
    __syncthreads();
    // block 0 publishes the global key offsets for main_kernel
    if (myb == 0) {
#pragma unroll
        for (int k = 0; k < 4; k++) {
            const int kk = tid * 4 + k;
            g_bs2[kk] = bs2s[kk];
        }
        if (tid == 0) g_bs2[NKEY] = NPART;
    }

    // ---- phase C: stable in-block ranks + scatter ----
#pragma unroll
    for (int k = 0; k < 4 * NKEY / 128; k++) ((int*)wcnt)[tid + k * 128] = 0;
    __syncthreads();
    const unsigned m = __match_any_sync(FULL, key);
    const int r = __popc(m & ((1u << lane) - 1u));
    if (r == 0) wcnt[w][key] = __popc(m);
    __syncthreads();
#pragma unroll
    for (int k = 0; k < NKEY / 128; k++) {
        const int t = tid + k * 128;
        int s = 0;
#pragma unroll
        for (int wi = 0; wi < 4; wi++) { const int v = wcnt[wi][t]; wcnt[wi][t] = s; s += v; }
    }
    __syncthreads();

    const int p = bs2s[key] + boffm[key] + wcnt[w][key] + r;
    g_pcs[p]      = pc;
    g_ps[2*p + 0] = pA;
    g_ps[2*p + 1] = pE;

    // ---- self-reset barrier counters for next replay ----
    __syncthreads();
    if (tid == 0) {
        const int v = atomicAdd(&g_bar2, 1);
        if (v == NBLK - 1) { g_bar1 = 0; g_bar2 = 0; __threadfence(); }
    }
}

// ---------------------------------------------------------------------------
// One warp per sample (R5 structure). Each lane owns ONE of the 32 cells
// actually needed: 8 trilinear corners + their 24 face neighbors.
// Accumulators are initialized from the H0/E0 base loads so those LDGs
// overlap the particle scan instead of sitting in the tail.
// ---------------------------------------------------------------------------
__global__ void __launch_bounds__(64)
main_kernel(const float* __restrict__ spos,
            const float* __restrict__ H0,
            const float* __restrict__ E0,
            float* __restrict__ out) {
    __shared__ float sv[2][5][64];
    const unsigned FULL = 0xffffffffu;
    const int wib  = threadIdx.x >> 5;
    const int lane = threadIdx.x & 31;
    const int s    = (blockIdx.x << 1) + wib;

    const float px = spos[3*s+0];
    const float py = spos[3*s+1];
    const float pz = spos[3*s+2];
    // grid axis0 <- comp2, axis1 <- comp1, axis2 <- comp0 (reference transpose)
    const float t0 = fminf(fmaxf((pz + 1.0f) * 63.5f, 0.0f), 127.0f);
    const float t1 = fminf(fmaxf((py + 1.0f) * 63.5f, 0.0f), 127.0f);
    const float t2 = fminf(fmaxf((px + 1.0f) * 63.5f, 0.0f), 127.0f);
    const int i0 = (int)floorf(t0); const float f0 = t0 - (float)i0;
    const int i1 = (int)floorf(t1); const float f1 = t1 - (float)i1;
    const int i2 = (int)floorf(t2); const float f2 = t2 - (float)i2;

    // lane -> block coords (b0,b1,b2), covering the 32 needed cells
    int b0, b1, b2;
    if (lane < 8) {
        b0 = 1 + ((lane >> 2) & 1); b1 = 1 + ((lane >> 1) & 1); b2 = 1 + (lane & 1);
    } else {
        const int idx = lane - 8, axis = idx >> 3, rest = idx & 7;
        const int s3 = ((rest >> 2) & 1) * 3;
        const int u = 1 + ((rest >> 1) & 1), v = 1 + (rest & 1);
        b0 = (axis == 0) ? s3 : u;
        b1 = (axis == 1) ? s3 : ((axis == 0) ? u : v);
        b2 = (axis == 2) ? s3 : v;
    }
    const int gc0 = min(max(i0 - 1 + b0, 0), 127);
    const int gc1 = min(max(i1 - 1 + b1, 0), 127);
    const int gc2 = min(max(i2 - 1 + b2, 0), 127);
    const float gcf0 = (float)gc0, gcf1 = (float)gc1, gcf2 = (float)gc2;
    const unsigned gcpack = (unsigned)(gc0 | (gc1 << 8) | (gc2 << 16));

    // particle-window (covers all 32 cells)
    const int lo0 = min(max(i0 - 1, 0), 127) - 9, hi0 = min(max(i0 + 2, 0), 127) + 9;
    const int lo1 = min(max(i1 - 1, 0), 127) - 9, hi1 = min(max(i1 + 2, 0), 127) + 9;
    const int lo2 = min(max(i2 - 1, 0), 127) - 9, hi2 = min(max(i2 + 2, 0), 127) + 9;
    const unsigned sp0 = (unsigned)(hi0 - lo0);
    const unsigned sp1 = (unsigned)(hi1 - lo1);
    const unsigned sp2 = (unsigned)(hi2 - lo2);

    const int r0  = max(lo0, 0) >> 1;
    const int r1  = min(hi0, 127) >> 1;
    const int slo = max(lo1, 0) >> 4;
    const int shi = min(hi1, 127) >> 4;

    // accumulators start from the base grid values (loads overlap the scan)
    const int flat = (gc0 * GDIM + gc1) * GDIM + gc2;
    float aH  = __ldg(&H0[flat]);
    float aE0 = __ldg(&E0[0*G3 + flat]);
    float aE1 = __ldg(&E0[1*G3 + flat]);
    float aE2 = __ldg(&E0[2*G3 + flat]);
    float aE3 = __ldg(&E0[3*G3 + flat]);

    for (int r = r0; r <= r1; r++) {
        const int rb = r << 3;
        const int j0 = g_bs2[rb + slo];
        const int j1 = g_bs2[rb + shi + 1];
        for (int base = j0 & ~31; base < j1; base += 32) {
            const int idx = base + lane;
            const int pcv = g_pcs[idx];
            const int c0 = pcv & 255, c1 = (pcv >> 8) & 255, c2 = (pcv >> 16) & 255;
            const bool hit = ((unsigned)(c0 - lo0) <= sp0) &
                             ((unsigned)(c1 - lo1) <= sp1) &
                             ((unsigned)(c2 - lo2) <= sp2) &
                             (idx >= j0) & (idx < j1);
            unsigned msk = __ballot_sync(FULL, hit);
            while (msk) {
                const int j = __ffs(msk) - 1;
                msk &= msk - 1;
                const int pcj = __shfl_sync(FULL, pcv, j);
                const float4 A  = __ldg(&g_ps[2*(base + j) + 0]);
                const float4 Em = __ldg(&g_ps[2*(base + j) + 1]);
                const unsigned diff = __vabsdiffu4((unsigned)pcj, gcpack);
                const bool in = (__vcmpleu4(diff, 0x09090909u) == 0xFFFFFFFFu);
                const float d0 = gcf0 - A.x;
                const float d1 = gcf1 - A.y;
                const float d2 = gcf2 - A.z;
                const float ssum = fmaf(d0, d0, fmaf(d1, d1, d2 * d2));
                const float e = __expf(ssum * -0.048828125f);
                float wv = in ? A.w : 0.0f;
                wv *= e;
                aH  += wv;
                aE0 += wv * Em.x;  aE1 += wv * Em.y;
                aE2 += wv * Em.z;  aE3 += wv * Em.w;
            }
        }
    }

    // stash the 32 needed cells in shared
    const int ci = b0 * 16 + b1 * 4 + b2;
    sv[wib][0][ci] = aH;
    sv[wib][1][ci] = aE0;
    sv[wib][2][ci] = aE1;
    sv[wib][3][ci] = aE2;
    sv[wib][4][ci] = aE3;
    __syncwarp();

    // diffusion step + ReLU + trilinear reduce (8 corner lanes)
#pragma unroll
    for (int ch = 0; ch < 5; ch++) {
        float part = 0.0f;
        if (lane < 8) {
            const int d0 = (lane >> 2) & 1, d1c = (lane >> 1) & 1, d2c = lane & 1;
            const int cc = (1 + d0) * 16 + (1 + d1c) * 4 + (1 + d2c);
            const float* v = sv[wib][ch];
            const float c = v[cc];
            const float lap = v[cc-16] + v[cc+16] + v[cc-4] + v[cc+4]
                            + v[cc-1]  + v[cc+1]  - 6.0f * c;
            float val;
            if (ch == 0) val = c * (1.0f - 5e-5f) + 0.002f * lap;
            else         val = c * (1.0f - 5e-5f) + 5e-5f + 0.001f * lap;
            val = fmaxf(val, 0.0f);
            const float wq = (d0  ? f0 : 1.0f - f0)
                           * (d1c ? f1 : 1.0f - f1)
                           * (d2c ? f2 : 1.0f - f2);
            part = val * wq;
        }
        part += __shfl_down_sync(FULL, part, 4);
        part += __shfl_down_sync(FULL, part, 2);
        part += __shfl_down_sync(FULL, part, 1);
        if (lane == 0) out[s * 5 + ch] = part;
    }
}

extern "C" void kernel_launch(void* const* d_in, const int* in_sizes, int n_in,
                              void* d_out, int out_size) {
    const float* positions   = (const float*)d_in[0];  // (4096,3)
    const float* intensities = (const float*)d_in[1];  // (4096,)
    const float* emotions    = (const float*)d_in[2];  // (4096,4)
    const float* sample_pos  = (const float*)d_in[3];  // (8,1024,3)
    const float* H0          = (const float*)d_in[4];  // (128,128,128)
    const float* E0          = (const float*)d_in[5];  // (4,128,128,128)
    float* out = (float*)d_out;                        // (8,1024,5)

    fsort_kernel<<<NBLK, 128>>>(positions, intensities, emotions);
    main_kernel<<<4096, 64>>>(sample_pos, H0, E0, out);
    (void)in_sizes; (void)n_in; (void)out_size;
}

// round 8
// speedup vs baseline: 1.1920x; 1.0192x over previous
#include <cuda_runtime.h>
#include <math.h>

#define GDIM 128
#define G3 (GDIM*GDIM*GDIM)
#define NPART 4096
#define NKEY 512           // 32 c0-bins (width 4) x 16 c1-subbins (width 8)
#define NBLK 32            // sort blocks (128 particles each)
#define SEGN 7             // max c0-bin segments per sample window

// Scratch (__device__ globals, no allocation)
__device__ float4 g_ps[NPART * 2];      // [2p]=(gp0,gp1,gp2,omega) [2p+1]=(em0..3)
__device__ int    g_pcs[NPART + 32];    // packed floor cell
__device__ int    g_bs2[NKEY + 1];      // key -> global start offset
__device__ int    g_hist[NBLK * NKEY];  // per-block key histograms
__device__ int    g_bar1;               // spin barrier (self-resetting)
__device__ int    g_bar2;

// ---------------------------------------------------------------------------
// Fused sort: hist + cross-block offsets + stable scatter in ONE kernel.
// 32 blocks x 128 threads; device spin barrier (32 blocks always co-resident).
// ---------------------------------------------------------------------------
__global__ void __launch_bounds__(128)
fsort_kernel(const float* __restrict__ pos,
             const float* __restrict__ inten,
             const float* __restrict__ emo) {
    __shared__ int h[NKEY];
    __shared__ int bs2s[NKEY];
    __shared__ int boffm[NKEY];
    __shared__ int wcnt[4][NKEY];
    __shared__ int wsum[4];
    const int tid  = threadIdx.x;
    const int w    = tid >> 5;
    const int lane = tid & 31;
    const int myb  = blockIdx.x;
    const unsigned FULL = 0xffffffffu;

#pragma unroll
    for (int k = 0; k < NKEY / 128; k++) h[tid + k * 128] = 0;
    __syncthreads();

    // ---- phase A: key + payload + block histogram ----
    const int i = myb * 128 + tid;
    const float gp0 = (pos[3*i+0] + 1.0f) * 63.5f;
    const float gp1 = (pos[3*i+1] + 1.0f) * 63.5f;
    const float gp2 = (pos[3*i+2] + 1.0f) * 63.5f;
    const int c0 = min(max((int)floorf(gp0), 0), GDIM-1);
    const int c1 = min(max((int)floorf(gp1), 0), GDIM-1);
    const int c2 = min(max((int)floorf(gp2), 0), GDIM-1);
    const int pc  = c0 | (c1 << 8) | (c2 << 16);
    const int key = ((c0 >> 2) << 4) | (c1 >> 3);
    atomicAdd(&h[key], 1);
    const float4 pA = make_float4(gp0, gp1, gp2, inten[i] * 0.01f);
    const float4 pE = make_float4(emo[4*i+0], emo[4*i+1], emo[4*i+2], emo[4*i+3]);
    __syncthreads();
#pragma unroll
    for (int k = 0; k < NKEY / 128; k++) {
        const int t = tid + k * 128;
        g_hist[myb * NKEY + t] = h[t];
    }
    __threadfence();

    // ---- barrier: all block histograms visible ----
    if (tid == 0) {
        atomicAdd(&g_bar1, 1);
        while (*(volatile int*)&g_bar1 < NBLK) { }
    }
    __syncthreads();
    __threadfence();

    // ---- phase B: per-key cross-block sums; thread t owns keys 4t..4t+3 ----
    int totk[4], bok[4];
#pragma unroll
    for (int k = 0; k < 4; k++) {
        const int kk = tid * 4 + k;
        int s = 0, mine = 0;
#pragma unroll
        for (int b = 0; b < NBLK; b++) {
            if (b == myb) mine = s;
            s += g_hist[b * NKEY + kk];
        }
        totk[k] = s; bok[k] = mine;
    }
    const int tsum = totk[0] + totk[1] + totk[2] + totk[3];
    int inc = tsum;
#pragma unroll
    for (int d = 1; d < 32; d <<= 1) {
        const int u = __shfl_up_sync(FULL, inc, d);
        if (lane >= d) inc += u;
    }
    if (lane == 31) wsum[w] = inc;
    __syncthreads();
    if (tid == 0) {
        int s = 0;
#pragma unroll
        for (int q = 0; q < 4; q++) { const int x = wsum[q]; wsum[q] = s; s += x; }
    }
    __syncthreads();
    int run = wsum[w] + inc - tsum;        // exclusive prefix for key 4*tid
#pragma unroll
    for (int k = 0; k < 4; k++) {
        const int kk = tid * 4 + k;
        bs2s[kk]  = run;
        boffm[kk] = bok[k];
        run += totk[k];
    }
    __syncthreads();
    if (myb == 0) {
#pragma unroll
        for (int k = 0; k < 4; k++) {
            const int kk = tid * 4 + k;
            g_bs2[kk] = bs2s[kk];
        }
        if (tid == 0) g_bs2[NKEY] = NPART;
    }

    // ---- phase C: stable in-block ranks + scatter ----
#pragma unroll
    for (int k = 0; k < 4 * NKEY / 128; k++) ((int*)wcnt)[tid + k * 128] = 0;
    __syncthreads();
    const unsigned m = __match_any_sync(FULL, key);
    const int r = __popc(m & ((1u << lane) - 1u));
    if (r == 0) wcnt[w][key] = __popc(m);
    __syncthreads();
#pragma unroll
    for (int k = 0; k < NKEY / 128; k++) {
        const int t = tid + k * 128;
        int s = 0;
#pragma unroll
        for (int wi = 0; wi < 4; wi++) { const int v = wcnt[wi][t]; wcnt[wi][t] = s; s += v; }
    }
    __syncthreads();

    const int p = bs2s[key] + boffm[key] + wcnt[w][key] + r;
    g_pcs[p]      = pc;
    g_ps[2*p + 0] = pA;
    g_ps[2*p + 1] = pE;

    // ---- self-reset barrier counters for next replay ----
    __syncthreads();
    if (tid == 0) {
        const int v = atomicAdd(&g_bar2, 1);
        if (v == NBLK - 1) { g_bar1 = 0; g_bar2 = 0; __threadfence(); }
    }
}

// ---------------------------------------------------------------------------
// One warp per sample. Each lane owns ONE of the 32 cells actually needed.
// All segment bounds + first-chunk cell words are prefetched in one MLP burst
// before the scan, so the scan exposes almost no load latency.
// ---------------------------------------------------------------------------
__global__ void __launch_bounds__(64)
main_kernel(const float* __restrict__ spos,
            const float* __restrict__ H0,
            const float* __restrict__ E0,
            float* __restrict__ out) {
    __shared__ float sv[2][5][64];
    const unsigned FULL = 0xffffffffu;
    const int wib  = threadIdx.x >> 5;
    const int lane = threadIdx.x & 31;
    const int s    = (blockIdx.x << 1) + wib;

    const float px = spos[3*s+0];
    const float py = spos[3*s+1];
    const float pz = spos[3*s+2];
    // grid axis0 <- comp2, axis1 <- comp1, axis2 <- comp0 (reference transpose)
    const float t0 = fminf(fmaxf((pz + 1.0f) * 63.5f, 0.0f), 127.0f);
    const float t1 = fminf(fmaxf((py + 1.0f) * 63.5f, 0.0f), 127.0f);
    const float t2 = fminf(fmaxf((px + 1.0f) * 63.5f, 0.0f), 127.0f);
    const int i0 = (int)floorf(t0); const float f0 = t0 - (float)i0;
    const int i1 = (int)floorf(t1); const float f1 = t1 - (float)i1;
    const int i2 = (int)floorf(t2); const float f2 = t2 - (float)i2;

    // lane -> block coords (b0,b1,b2), covering the 32 needed cells
    int b0, b1, b2;
    if (lane < 8) {
        b0 = 1 + ((lane >> 2) & 1); b1 = 1 + ((lane >> 1) & 1); b2 = 1 + (lane & 1);
    } else {
        const int idx = lane - 8, axis = idx >> 3, rest = idx & 7;
        const int s3 = ((rest >> 2) & 1) * 3;
        const int u = 1 + ((rest >> 1) & 1), v = 1 + (rest & 1);
        b0 = (axis == 0) ? s3 : u;
        b1 = (axis == 1) ? s3 : ((axis == 0) ? u : v);
        b2 = (axis == 2) ? s3 : v;
    }
    const int gc0 = min(max(i0 - 1 + b0, 0), 127);
    const int gc1 = min(max(i1 - 1 + b1, 0), 127);
    const int gc2 = min(max(i2 - 1 + b2, 0), 127);
    const float gcf0 = (float)gc0, gcf1 = (float)gc1, gcf2 = (float)gc2;
    const unsigned gcpack = (unsigned)(gc0 | (gc1 << 8) | (gc2 << 16));

    // particle-window (covers all 32 cells)
    const int lo0 = min(max(i0 - 1, 0), 127) - 9, hi0 = min(max(i0 + 2, 0), 127) + 9;
    const int lo1 = min(max(i1 - 1, 0), 127) - 9, hi1 = min(max(i1 + 2, 0), 127) + 9;
    const int lo2 = min(max(i2 - 1, 0), 127) - 9, hi2 = min(max(i2 + 2, 0), 127) + 9;
    const unsigned sp0 = (unsigned)(hi0 - lo0);
    const unsigned sp1 = (unsigned)(hi1 - lo1);
    const unsigned sp2 = (unsigned)(hi2 - lo2);

    const int r0  = max(lo0, 0) >> 2;
    const int r1  = min(hi0, 127) >> 2;
    const int slo = max(lo1, 0) >> 3;
    const int shi = min(hi1, 127) >> 3;
    const int nseg = r1 - r0;              // 0..6 inclusive extra segments

    // ---- one MLP burst: all segment bounds + first-chunk cell words ----
    int jj0[SEGN], jj1[SEGN], pv[SEGN];
#pragma unroll
    for (int k = 0; k < SEGN; k++) {
        const bool val = (k <= nseg);
        const int rb = (r0 + k) << 4;
        jj0[k] = val ? __ldg(&g_bs2[rb + slo])     : 0;
        jj1[k] = val ? __ldg(&g_bs2[rb + shi + 1]) : 0;
    }
#pragma unroll
    for (int k = 0; k < SEGN; k++) {
        const bool val = (k <= nseg);
        pv[k] = __ldg(&g_pcs[(val ? (jj0[k] & ~31) : 0) + lane]);
    }

    // accumulators start from the base grid values (loads overlap the scan)
    const int flat = (gc0 * GDIM + gc1) * GDIM + gc2;
    float aH  = __ldg(&H0[flat]);
    float aE0 = __ldg(&E0[0*G3 + flat]);
    float aE1 = __ldg(&E0[1*G3 + flat]);
    float aE2 = __ldg(&E0[2*G3 + flat]);
    float aE3 = __ldg(&E0[3*G3 + flat]);

#pragma unroll
    for (int k = 0; k < SEGN; k++) {
        if (k > nseg) break;
        const int j0 = jj0[k], j1 = jj1[k];
        int base = j0 & ~31;
        int pcv  = pv[k];
        while (true) {
            const int  nbase = base + 32;
            const bool more  = nbase < j1;
            int npcv = 0;
            if (more) npcv = __ldg(&g_pcs[nbase + lane]);   // prefetch next chunk
            const int idx = base + lane;
            const int c0 = pcv & 255, c1 = (pcv >> 8) & 255, c2 = (pcv >> 16) & 255;
            const bool hit = ((unsigned)(c0 - lo0) <= sp0) &
                             ((unsigned)(c1 - lo1) <= sp1) &
                             ((unsigned)(c2 - lo2) <= sp2) &
                             (idx >= j0) & (idx < j1);
            unsigned msk = __ballot_sync(FULL, hit);
            while (msk) {
                const int j = __ffs(msk) - 1;
                msk &= msk - 1;
                const int pcj = __shfl_sync(FULL, pcv, j);
                const float4 A  = __ldg(&g_ps[2*(base + j) + 0]);
                const float4 Em = __ldg(&g_ps[2*(base + j) + 1]);
                const unsigned diff = __vabsdiffu4((unsigned)pcj, gcpack);
                const bool in = (__vcmpleu4(diff, 0x09090909u) == 0xFFFFFFFFu);
                const float d0 = gcf0 - A.x;
                const float d1 = gcf1 - A.y;
                const float d2 = gcf2 - A.z;
                const float ssum = fmaf(d0, d0, fmaf(d1, d1, d2 * d2));
                const float e = __expf(ssum * -0.048828125f);
                float wv = in ? A.w : 0.0f;
                wv *= e;
                aH  += wv;
                aE0 += wv * Em.x;  aE1 += wv * Em.y;
                aE2 += wv * Em.z;  aE3 += wv * Em.w;
            }
            if (!more) break;
            base = nbase; pcv = npcv;
        }
    }

    // stash the 32 needed cells in shared
    const int ci = b0 * 16 + b1 * 4 + b2;
    sv[wib][0][ci] = aH;
    sv[wib][1][ci] = aE0;
    sv[wib][2][ci] = aE1;
    sv[wib][3][ci] = aE2;
    sv[wib][4][ci] = aE3;
    __syncwarp();

    // diffusion step + ReLU + trilinear reduce (8 corner lanes)
#pragma unroll
    for (int ch = 0; ch < 5; ch++) {
        float part = 0.0f;
        if (lane < 8) {
            const int d0 = (lane >> 2) & 1, d1c = (lane >> 1) & 1, d2c = lane & 1;
            const int cc = (1 + d0) * 16 + (1 + d1c) * 4 + (1 + d2c);
            const float* v = sv[wib][ch];
            const float c = v[cc];
            const float lap = v[cc-16] + v[cc+16] + v[cc-4] + v[cc+4]
                            + v[cc-1]  + v[cc+1]  - 6.0f * c;
            float val;
            if (ch == 0) val = c * (1.0f - 5e-5f) + 0.002f * lap;
            else         val = c * (1.0f - 5e-5f) + 5e-5f + 0.001f * lap;
            val = fmaxf(val, 0.0f);
            const float wq = (d0  ? f0 : 1.0f - f0)
                           * (d1c ? f1 : 1.0f - f1)
                           * (d2c ? f2 : 1.0f - f2);
            part = val * wq;
        }
        part += __shfl_down_sync(FULL, part, 4);
        part += __shfl_down_sync(FULL, part, 2);
        part += __shfl_down_sync(FULL, part, 1);
        if (lane == 0) out[s * 5 + ch] = part;
    }
}

extern "C" void kernel_launch(void* const* d_in, const int* in_sizes, int n_in,
                              void* d_out, int out_size) {
    const float* positions   = (const float*)d_in[0];  // (4096,3)
    const float* intensities = (const float*)d_in[1];  // (4096,)
    const float* emotions    = (const float*)d_in[2];  // (4096,4)
    const float* sample_pos  = (const float*)d_in[3];  // (8,1024,3)
    const float* H0          = (const float*)d_in[4];  // (128,128,128)
    const float* E0          = (const float*)d_in[5];  // (4,128,128,128)
    float* out = (float*)d_out;                        // (8,1024,5)

    fsort_kernel<<<NBLK, 128>>>(positions, intensities, emotions);
    main_kernel<<<4096, 64>>>(sample_pos, H0, E0, out);
    (void)in_sizes; (void)n_in; (void)out_size;
}